// round 10
// baseline (speedup 1.0000x reference)
#include <cuda_runtime.h>
#include <math.h>
#include <math_constants.h>
#include <cstdint>

#define BATCH  4
#define SEQ    2048
#define DMODEL 1024
#define NHEADS 16
#define DHEAD  64

// Scratch (device globals — allocation-free per harness rules)
// g_q, g_k, g_attn, g_xr, g_w1r, g_w2r are k-pair-PERMUTED along their
// contraction dims (p(k)=((k&3)<<1)|(k>>2) within 8-groups). g_v is plain.
__device__ float g_q[(size_t)BATCH * NHEADS * SEQ * DHEAD];
__device__ float g_k[(size_t)BATCH * NHEADS * SEQ * DHEAD];
__device__ float g_v[(size_t)BATCH * NHEADS * SEQ * DHEAD];
__device__ float g_attn[(size_t)BATCH * SEQ * DMODEL];
__device__ float g_xr[(size_t)BATCH * SEQ * DMODEL];
__device__ float g_w1r[(size_t)3 * DMODEL * DMODEL];
__device__ float g_w2r[(size_t)DMODEL * DMODEL];

// ---------------------------------------------------------------------------
// helpers
// ---------------------------------------------------------------------------
__device__ __forceinline__ float tf32r(float x) {
    float r;
    asm("cvt.rna.tf32.f32 %0, %1;" : "=f"(r) : "f"(x));
    return r;
}

__device__ __forceinline__ uint32_t fbits(float x) { return __float_as_uint(x); }

__device__ __forceinline__ uint32_t smem_u32(const void* p) {
    uint32_t a;
    asm("{ .reg .u64 t; cvta.to.shared.u64 t, %1; cvt.u32.u64 %0, t; }"
        : "=r"(a) : "l"(p));
    return a;
}

__device__ __forceinline__ void cp16(uint32_t dst, const float* src) {
    asm volatile("cp.async.cg.shared.global [%0], [%1], 16;"
                 :: "r"(dst), "l"(src));
}

#define CP_COMMIT()  asm volatile("cp.async.commit_group;" ::: "memory")
#define CP_WAIT(n)   asm volatile("cp.async.wait_group %0;" :: "n"(n) : "memory")

// D = A(16x8 tf32, row) * B(8x8 tf32, col) + D   (f32 accum)
__device__ __forceinline__ void mma_tf32(float c[4],
                                         uint32_t a0, uint32_t a1,
                                         uint32_t a2, uint32_t a3,
                                         uint32_t b0, uint32_t b1) {
    asm volatile(
        "mma.sync.aligned.m16n8k8.row.col.f32.tf32.tf32.f32 "
        "{%0,%1,%2,%3}, {%4,%5,%6,%7}, {%8,%9}, {%0,%1,%2,%3};"
        : "+f"(c[0]), "+f"(c[1]), "+f"(c[2]), "+f"(c[3])
        : "r"(a0), "r"(a1), "r"(a2), "r"(a3), "r"(b0), "r"(b1));
}

// ---------------------------------------------------------------------------
// one-time TF32 round + k-pair permutation (8 floats per thread)
// out[base + p(k)] = tf32(in[base + k]),  p(k) = ((k&3)<<1)|(k>>2)
// ---------------------------------------------------------------------------
__global__ __launch_bounds__(256) void round_perm_k(
    const float* __restrict__ s, float* __restrict__ d, int ngrp)
{
    int i = blockIdx.x * blockDim.x + threadIdx.x;
    if (i < ngrp) {
        float4 v0 = *(const float4*)(s + (size_t)i * 8);
        float4 v1 = *(const float4*)(s + (size_t)i * 8 + 4);
        float* o = d + (size_t)i * 8;
        o[0] = tf32r(v0.x);   // k=0 -> 0
        o[2] = tf32r(v0.y);   // k=1 -> 2
        o[4] = tf32r(v0.z);   // k=2 -> 4
        o[6] = tf32r(v0.w);   // k=3 -> 6
        o[1] = tf32r(v1.x);   // k=4 -> 1
        o[3] = tf32r(v1.y);   // k=5 -> 3
        o[5] = tf32r(v1.z);   // k=6 -> 5
        o[7] = tf32r(v1.w);   // k=7 -> 7
    }
}

// ===========================================================================
// TF32 mma.sync GEMM (NT), inputs k-pair-permuted: LDS.64 fragment loads.
// 128x128x16 CTA tile, 256 thr = 8 warps (4m x 2n), warptile 32x64.
// 4-stage cp.async, one __syncthreads per stage. Stride 24 (8B conflict-free).
// MODE 0: scatter Q(perm,scaled)/K(perm)/V(plain). MODE 1: C plain.
// ===========================================================================
#define GBK  16
#define BKP  24
#define GBM  128
#define GBN  128
#define STG  4
#define GEMM_SMEM ((STG * GBM * BKP + STG * GBN * BKP) * 4)   // 98304

template <int MODE>
__global__ __launch_bounds__(256, 2) void gemm_mma(
    const float* __restrict__ W, const float* __restrict__ bias,
    float* __restrict__ C, int M, int N, int K)
{
    extern __shared__ float smg[];
    float* As = smg;
    float* Bs = smg + STG * GBM * BKP;

    const int tid  = threadIdx.x;
    const int lane = tid & 31;
    const int g    = lane >> 2;
    const int t    = lane & 3;
    const int wid  = tid >> 5;
    const int wm   = (wid & 3) * 32;
    const int wn   = (wid >> 2) * 64;
    const int bm   = blockIdx.y;
    const int bn   = blockIdx.x;

    const float* Ag = (MODE == 1) ? g_attn : g_xr;

    const int srow = tid >> 1;
    const int sch  = (tid & 1) * 8;
    const float* Asrc = Ag + (size_t)(bm * GBM + srow) * K + sch;
    const float* Bsrc = W  + (size_t)(bn * GBN + srow) * K + sch;

    const uint32_t aDst = smem_u32(As) + (srow * BKP + sch) * 4;
    const uint32_t bDst = smem_u32(Bs) + (srow * BKP + sch) * 4;

    float acc[2][8][4];
    #pragma unroll
    for (int mt = 0; mt < 2; mt++)
        #pragma unroll
        for (int nt = 0; nt < 8; nt++)
            #pragma unroll
            for (int e = 0; e < 4; e++) acc[mt][nt][e] = 0.0f;

    const int NS = K / GBK;

    #pragma unroll
    for (int st = 0; st < 3; st++) {
        const int k0 = st * GBK;
        cp16(aDst + st * GBM * BKP * 4,      Asrc + k0);
        cp16(aDst + st * GBM * BKP * 4 + 16, Asrc + k0 + 4);
        cp16(bDst + st * GBN * BKP * 4,      Bsrc + k0);
        cp16(bDst + st * GBN * BKP * 4 + 16, Bsrc + k0 + 4);
        CP_COMMIT();
    }

    for (int s = 0; s < NS; s++) {
        const int buf = s & 3;
        CP_WAIT(2);
        __syncthreads();

        if (s + 3 < NS) {
            const int nbuf = (s + 3) & 3;
            const int k0 = (s + 3) * GBK;
            cp16(aDst + nbuf * GBM * BKP * 4,      Asrc + k0);
            cp16(aDst + nbuf * GBM * BKP * 4 + 16, Asrc + k0 + 4);
            cp16(bDst + nbuf * GBN * BKP * 4,      Bsrc + k0);
            cp16(bDst + nbuf * GBN * BKP * 4 + 16, Bsrc + k0 + 4);
        }
        CP_COMMIT();

        const float* Asb = &As[buf * GBM * BKP];
        const float* Bsb = &Bs[buf * GBN * BKP];

        #pragma unroll
        for (int kk = 0; kk < 2; kk++) {
            // A fragments: one LDS.64 per row-half per m-tile
            float2 alo[2], ahi[2];
            #pragma unroll
            for (int mt = 0; mt < 2; mt++) {
                const float* base = &Asb[(wm + mt * 16) * BKP + kk * 8 + 2 * t];
                alo[mt] = *(const float2*)&base[g * BKP];
                ahi[mt] = *(const float2*)&base[(g + 8) * BKP];
            }
            #pragma unroll
            for (int nt = 0; nt < 8; nt++) {
                const float2 bp =
                    *(const float2*)&Bsb[(wn + nt * 8 + g) * BKP + kk * 8 + 2 * t];
                #pragma unroll
                for (int mt = 0; mt < 2; mt++)
                    mma_tf32(acc[mt][nt],
                             fbits(alo[mt].x), fbits(ahi[mt].x),
                             fbits(alo[mt].y), fbits(ahi[mt].y),
                             fbits(bp.x), fbits(bp.y));
            }
        }
    }

    // ---- epilogue ----
    const float QSC = 0.125f * 1.4426950408889634f;
    // permuted local positions for columns 2t and 2t+1
    const int plo = (((2 * t) & 3) << 1) | (t >> 1);
    const int phi = (((2 * t + 1) & 3) << 1) | ((2 * t + 1) >> 2);
    #pragma unroll
    for (int mt = 0; mt < 2; mt++) {
        #pragma unroll
        for (int half = 0; half < 2; half++) {
            const int m = bm * GBM + wm + mt * 16 + g + half * 8;
            const int bb_ = m >> 11;
            const int srw = m & 2047;
            #pragma unroll
            for (int nt = 0; nt < 8; nt++) {
                const int n = bn * GBN + wn + nt * 8 + 2 * t;
                float2 bvv = *(const float2*)(bias + n);
                float2 v;
                v.x = acc[mt][nt][half * 2 + 0] + bvv.x;
                v.y = acc[mt][nt][half * 2 + 1] + bvv.y;
                if (MODE == 0) {
                    const int part = n >> 10;
                    const int hd = n & 1023;
                    const int hh = hd >> 6;
                    const int d = hd & 63;
                    const size_t rowoff =
                        (((size_t)(bb_ * NHEADS + hh)) * SEQ + srw) * DHEAD;
                    if (part == 0) {            // Q: scale+round, permuted
                        const int dg = d - 2 * t;
                        g_q[rowoff + dg + plo] = tf32r(v.x * QSC);
                        g_q[rowoff + dg + phi] = tf32r(v.y * QSC);
                    } else if (part == 1) {     // K: round, permuted
                        const int dg = d - 2 * t;
                        g_k[rowoff + dg + plo] = tf32r(v.x);
                        g_k[rowoff + dg + phi] = tf32r(v.y);
                    } else {                    // V: round, plain
                        v.x = tf32r(v.x);
                        v.y = tf32r(v.y);
                        *(float2*)(g_v + rowoff + d) = v;
                    }
                } else {
                    *(float2*)(C + (size_t)m * N + n) = v;
                }
            }
        }
    }
}

// ===========================================================================
// Flash attention, TF32 mma.sync, LDS.64 fragments via k-pair permutation.
// Q/K permuted along d (from QKV epilogue), V plain. P stored key-permuted.
// 128-row q-tile, 256 thr = 8 warps x 16 q-rows. Base-2 softmax.
// Strides 72 floats (8B-phase conflict-free).
// ===========================================================================
#define FSTR 72
#define QTILE 128
#define FLASH_SMEM ((64 * FSTR + 64 * FSTR + QTILE * FSTR + QTILE * FSTR) * 4)

__global__ __launch_bounds__(256) void flash_mma(const int* __restrict__ maskFlag)
{
    extern __shared__ float smf[];
    float* Ks = smf;                    // [64 keys][FSTR]  (d permuted)
    float* Vs = Ks + 64 * FSTR;         // [64 keys][FSTR]  (plain)
    float* Qs = Vs + 64 * FSTR;         // [128 q][FSTR]    (d permuted)
    float* Ps = Qs + QTILE * FSTR;      // [128 q][FSTR]    (key permuted)

    const int tid  = threadIdx.x;
    const int lane = tid & 31;
    const int w    = tid >> 5;
    const int g    = lane >> 2;
    const int t    = lane & 3;
    const int qt   = (int)gridDim.x - 1 - (int)blockIdx.x;
    const int h    = blockIdx.y;
    const int b    = blockIdx.z;
    const int causal = maskFlag[0];

    const size_t bh = (size_t)(b * NHEADS + h) * SEQ * DHEAD;
    const float* Qg = g_q + bh + (size_t)qt * QTILE * DHEAD;
    const float* Kg = g_k + bh;
    const float* Vg = g_v + bh;

    const uint32_t ksU = smem_u32(Ks);
    const uint32_t vsU = smem_u32(Vs);
    const uint32_t qsU = smem_u32(Qs);

    const int plo = (((2 * t) & 3) << 1) | (t >> 1);
    const int phi = (((2 * t + 1) & 3) << 1) | ((2 * t + 1) >> 2);

    // ---- stage Q (already permuted+scaled+rounded) ----
    #pragma unroll
    for (int j = 0; j < 8; j++) {
        const int i = tid + j * 256;
        const int r  = i >> 4;
        const int c4 = (i & 15) * 4;
        cp16(qsU + (r * FSTR + c4) * 4, Qg + r * 64 + c4);
    }
    CP_COMMIT();

    float of[8][4];
    float mA = -CUDART_INF_F, mB = -CUDART_INF_F;
    float lA = 0.0f, lB = 0.0f;
    #pragma unroll
    for (int nt = 0; nt < 8; nt++)
        #pragma unroll
        for (int e = 0; e < 4; e++) of[nt][e] = 0.0f;

    const int ktEnd = causal ? (2 * qt + 1) : (SEQ / 64 - 1);

    for (int kt = 0; kt <= ktEnd; kt++) {
        __syncthreads();
        const float* Kt = Kg + (size_t)kt * 64 * DHEAD;
        const float* Vp = Vg + (size_t)kt * 64 * DHEAD;
        #pragma unroll
        for (int j = 0; j < 4; j++) {
            const int i = tid + j * 256;
            const int r  = i >> 4;
            const int c4 = (i & 15) * 4;
            cp16(ksU + (r * FSTR + c4) * 4, Kt + r * 64 + c4);
            cp16(vsU + (r * FSTR + c4) * 4, Vp + r * 64 + c4);
        }
        CP_COMMIT();
        CP_WAIT(0);
        __syncthreads();

        // ---- S = Q K^T (m16 x n64, k=64), LDS.64 fragments ----
        float sf[8][4];
        #pragma unroll
        for (int nt = 0; nt < 8; nt++)
            #pragma unroll
            for (int e = 0; e < 4; e++) sf[nt][e] = 0.0f;

        #pragma unroll
        for (int k8 = 0; k8 < 8; k8++) {
            const float* qb = &Qs[(w * 16) * FSTR + k8 * 8 + 2 * t];
            const float2 qlo = *(const float2*)&qb[g * FSTR];
            const float2 qhi = *(const float2*)&qb[(g + 8) * FSTR];
            #pragma unroll
            for (int nt = 0; nt < 8; nt++) {
                const float2 kb =
                    *(const float2*)&Ks[(nt * 8 + g) * FSTR + k8 * 8 + 2 * t];
                mma_tf32(sf[nt], fbits(qlo.x), fbits(qhi.x),
                         fbits(qlo.y), fbits(qhi.y), fbits(kb.x), fbits(kb.y));
            }
        }

        // ---- causal mask ----
        if (causal && (kt >= 2 * qt)) {
            const int rowb = qt * QTILE + w * 16;
            const int colb = kt * 64;
            #pragma unroll
            for (int nt = 0; nt < 8; nt++) {
                #pragma unroll
                for (int e = 0; e < 4; e++) {
                    const int col = colb + nt * 8 + 2 * t + (e & 1);
                    const int row = rowb + g + ((e >> 1) << 3);
                    if (col > row) sf[nt][e] = -CUDART_INF_F;
                }
            }
        }

        // ---- online softmax in base 2 (rows: A = g, B = g+8) ----
        float mxA = -CUDART_INF_F, mxB = -CUDART_INF_F;
        #pragma unroll
        for (int nt = 0; nt < 8; nt++) {
            mxA = fmaxf(mxA, fmaxf(sf[nt][0], sf[nt][1]));
            mxB = fmaxf(mxB, fmaxf(sf[nt][2], sf[nt][3]));
        }
        mxA = fmaxf(mxA, __shfl_xor_sync(0xffffffffu, mxA, 1));
        mxA = fmaxf(mxA, __shfl_xor_sync(0xffffffffu, mxA, 2));
        mxB = fmaxf(mxB, __shfl_xor_sync(0xffffffffu, mxB, 1));
        mxB = fmaxf(mxB, __shfl_xor_sync(0xffffffffu, mxB, 2));

        const float mnA = fmaxf(mA, mxA);
        const float mnB = fmaxf(mB, mxB);
        const float aA = exp2f(mA - mnA);
        const float aB = exp2f(mB - mnB);
        float sA = 0.0f, sB = 0.0f;
        #pragma unroll
        for (int nt = 0; nt < 8; nt++) {
            sf[nt][0] = exp2f(sf[nt][0] - mnA);
            sf[nt][1] = exp2f(sf[nt][1] - mnA);
            sf[nt][2] = exp2f(sf[nt][2] - mnB);
            sf[nt][3] = exp2f(sf[nt][3] - mnB);
            sA += sf[nt][0] + sf[nt][1];
            sB += sf[nt][2] + sf[nt][3];
        }
        sA += __shfl_xor_sync(0xffffffffu, sA, 1);
        sA += __shfl_xor_sync(0xffffffffu, sA, 2);
        sB += __shfl_xor_sync(0xffffffffu, sB, 1);
        sB += __shfl_xor_sync(0xffffffffu, sB, 2);
        lA = lA * aA + sA;
        lB = lB * aB + sB;
        mA = mnA;
        mB = mnB;
        #pragma unroll
        for (int nt = 0; nt < 8; nt++) {
            of[nt][0] *= aA; of[nt][1] *= aA;
            of[nt][2] *= aB; of[nt][3] *= aB;
        }

        // ---- write P (warp-private rows, key-permuted positions) ----
        #pragma unroll
        for (int nt = 0; nt < 8; nt++) {
            float* p0 = &Ps[(w * 16 + g) * FSTR + nt * 8];
            float* p1 = &Ps[(w * 16 + g + 8) * FSTR + nt * 8];
            p0[plo] = tf32r(sf[nt][0]); p0[phi] = tf32r(sf[nt][1]);
            p1[plo] = tf32r(sf[nt][2]); p1[phi] = tf32r(sf[nt][3]);
        }
        __syncwarp();

        // ---- O += P V (m16 x n64, k=64); P pairs via LDS.64, V plain ----
        #pragma unroll
        for (int k8 = 0; k8 < 8; k8++) {
            const float* pb = &Ps[(w * 16) * FSTR + k8 * 8 + 2 * t];
            const float2 pl = *(const float2*)&pb[g * FSTR];
            const float2 ph = *(const float2*)&pb[(g + 8) * FSTR];
            #pragma unroll
            for (int nt = 0; nt < 8; nt++) {
                const uint32_t b0 = fbits(Vs[(k8 * 8 + t) * FSTR + nt * 8 + g]);
                const uint32_t b1 = fbits(Vs[(k8 * 8 + t + 4) * FSTR + nt * 8 + g]);
                mma_tf32(of[nt], fbits(pl.x), fbits(ph.x),
                         fbits(pl.y), fbits(ph.y), b0, b1);
            }
        }
    }

    // ---- epilogue: normalize, round, store PERMUTED (A of out-proj) ----
    const float iA = 1.0f / lA;
    const float iB = 1.0f / lB;
    const int qrow = qt * QTILE + w * 16;
    #pragma unroll
    for (int nt = 0; nt < 8; nt++) {
        const int dg = h * 64 + nt * 8;     // 8-group base
        float* r0 = g_attn + ((size_t)b * SEQ + qrow + g) * DMODEL + dg;
        float* r1 = g_attn + ((size_t)b * SEQ + qrow + g + 8) * DMODEL + dg;
        r0[plo] = tf32r(of[nt][0] * iA); r0[phi] = tf32r(of[nt][1] * iA);
        r1[plo] = tf32r(of[nt][2] * iB); r1[phi] = tf32r(of[nt][3] * iB);
    }
}

// ---------------------------------------------------------------------------
extern "C" void kernel_launch(void* const* d_in, const int* in_sizes, int n_in,
                              void* d_out, int out_size)
{
    const float* x   = (const float*)d_in[0];
    const float* w1  = (const float*)d_in[1];
    const float* b1  = (const float*)d_in[2];
    const float* w2  = (const float*)d_in[3];
    const float* b2  = (const float*)d_in[4];
    const int*   msk = (const int*)  d_in[5];
    float* out = (float*)d_out;

    const int M = BATCH * SEQ;   // 8192

    cudaFuncSetAttribute(gemm_mma<0>,
                         cudaFuncAttributeMaxDynamicSharedMemorySize, GEMM_SMEM);
    cudaFuncSetAttribute(gemm_mma<1>,
                         cudaFuncAttributeMaxDynamicSharedMemorySize, GEMM_SMEM);
    cudaFuncSetAttribute(flash_mma,
                         cudaFuncAttributeMaxDynamicSharedMemorySize, FLASH_SMEM);

    // 0) pre-round + k-pair-permute inputs
    float* d_xr;  cudaGetSymbolAddress((void**)&d_xr,  g_xr);
    float* d_w1r; cudaGetSymbolAddress((void**)&d_w1r, g_w1r);
    float* d_w2r; cudaGetSymbolAddress((void**)&d_w2r, g_w2r);
    {
        const int nx = M * DMODEL / 8;
        round_perm_k<<<(nx + 255) / 256, 256>>>(x, d_xr, nx);
        const int n1 = 3 * DMODEL * DMODEL / 8;
        round_perm_k<<<(n1 + 255) / 256, 256>>>(w1, d_w1r, n1);
        const int n2 = DMODEL * DMODEL / 8;
        round_perm_k<<<(n2 + 255) / 256, 256>>>(w2, d_w2r, n2);
    }

    // 1) QKV projection -> g_q/g_k (permuted) / g_v (plain)
    gemm_mma<0><<<dim3(3 * DMODEL / GBN, M / GBM), 256, GEMM_SMEM>>>(
        d_w1r, b1, nullptr, M, 3 * DMODEL, DMODEL);

    // 2) Flash attention -> g_attn (permuted)
    flash_mma<<<dim3(SEQ / QTILE, NHEADS, BATCH), 256, FLASH_SMEM>>>(msk);

    // 3) Output projection -> d_out (plain)
    gemm_mma<1><<<dim3(DMODEL / GBN, M / GBM), 256, GEMM_SMEM>>>(
        d_w2r, b2, out, M, DMODEL, DMODEL);
}

// round 11
// speedup vs baseline: 1.8845x; 1.8845x over previous
#include <cuda_runtime.h>
#include <cuda_fp16.h>
#include <math.h>
#include <math_constants.h>
#include <cstdint>

#define BATCH  4
#define SEQ    2048
#define DMODEL 1024
#define NHEADS 16
#define DHEAD  64

// Scratch (device globals — allocation-free per harness rules)
__device__ __half g_qh[(size_t)BATCH * NHEADS * SEQ * DHEAD];   // [b,h,s,d] scaled
__device__ __half g_kh[(size_t)BATCH * NHEADS * SEQ * DHEAD];   // [b,h,s,d]
__device__ __half g_vt[(size_t)BATCH * NHEADS * DHEAD * SEQ];   // [b,h,d,s] (transposed)
__device__ __half g_attnh[(size_t)BATCH * SEQ * DMODEL];        // [b,s,dm]
__device__ __half g_xh[(size_t)BATCH * SEQ * DMODEL];           // x fp16
__device__ __half g_w1h[(size_t)3 * DMODEL * DMODEL];           // w1 fp16
__device__ __half g_w2h[(size_t)DMODEL * DMODEL];               // w2 fp16

// ---------------------------------------------------------------------------
// helpers
// ---------------------------------------------------------------------------
__device__ __forceinline__ uint32_t smem_u32(const void* p) {
    uint32_t a;
    asm("{ .reg .u64 t; cvta.to.shared.u64 t, %1; cvt.u32.u64 %0, t; }"
        : "=r"(a) : "l"(p));
    return a;
}

__device__ __forceinline__ void cp16(uint32_t dst, const void* src) {
    asm volatile("cp.async.cg.shared.global [%0], [%1], 16;"
                 :: "r"(dst), "l"(src));
}

#define CP_COMMIT()  asm volatile("cp.async.commit_group;" ::: "memory")
#define CP_WAIT(n)   asm volatile("cp.async.wait_group %0;" :: "n"(n) : "memory")

__device__ __forceinline__ uint32_t lds32(const __half* p) {
    return *(const uint32_t*)p;
}

// D = A(16x16 f16, row) * B(16x8 f16, col) + D   (f32 accum)
__device__ __forceinline__ void mma_f16(float c[4],
                                        uint32_t a0, uint32_t a1,
                                        uint32_t a2, uint32_t a3,
                                        uint32_t b0, uint32_t b1) {
    asm volatile(
        "mma.sync.aligned.m16n8k16.row.col.f32.f16.f16.f32 "
        "{%0,%1,%2,%3}, {%4,%5,%6,%7}, {%8,%9}, {%0,%1,%2,%3};"
        : "+f"(c[0]), "+f"(c[1]), "+f"(c[2]), "+f"(c[3])
        : "r"(a0), "r"(a1), "r"(a2), "r"(a3), "r"(b0), "r"(b1));
}

// ---------------------------------------------------------------------------
// one-time fp32 -> fp16 conversion (8 floats / thread)
// ---------------------------------------------------------------------------
__global__ __launch_bounds__(256) void to_f16_k(
    const float* __restrict__ s, __half* __restrict__ d, int ngrp)
{
    int i = blockIdx.x * blockDim.x + threadIdx.x;
    if (i < ngrp) {
        float4 v0 = *(const float4*)(s + (size_t)i * 8);
        float4 v1 = *(const float4*)(s + (size_t)i * 8 + 4);
        __half2* o = (__half2*)(d + (size_t)i * 8);
        o[0] = __floats2half2_rn(v0.x, v0.y);
        o[1] = __floats2half2_rn(v0.z, v0.w);
        o[2] = __floats2half2_rn(v1.x, v1.y);
        o[3] = __floats2half2_rn(v1.z, v1.w);
    }
}

// ===========================================================================
// FP16 mma.sync GEMM (NT): C[m,n] = sum_k A[m,k] * W[n,k] + bias[n]
// 128x128x32 CTA tile, 256 thr = 8 warps (4m x 2n), warptile 32x64.
// 4-stage cp.async, one __syncthreads per stage. Stride 40 halves.
// MODE 0: A = g_xh, scatter Q(fp16 scaled)/K(fp16)/V(fp16 TRANSPOSED).
// MODE 1: A = g_attnh, C = fp32 out.
// ===========================================================================
#define GBK   32
#define BKPH  40          // padded stride in halves
#define GBM   128
#define GBN   128
#define STG   4
#define GEMM_SMEM ((STG * GBM * BKPH + STG * GBN * BKPH) * 2)   // 81920

template <int MODE>
__global__ __launch_bounds__(256, 2) void gemm_mma(
    const __half* __restrict__ W, const float* __restrict__ bias,
    float* __restrict__ C, int M, int N, int K)
{
    extern __shared__ __half smg[];
    __half* As = smg;                          // [STG][GBM*BKPH]
    __half* Bs = smg + STG * GBM * BKPH;       // [STG][GBN*BKPH]

    const int tid  = threadIdx.x;
    const int lane = tid & 31;
    const int g    = lane >> 2;
    const int t    = lane & 3;
    const int wid  = tid >> 5;
    const int wm   = (wid & 3) * 32;
    const int wn   = (wid >> 2) * 64;
    const int bm   = blockIdx.y;
    const int bn   = blockIdx.x;

    const __half* Ag = (MODE == 1) ? g_attnh : g_xh;

    // staging: thread owns row tid>>1, halves (tid&1)*16 .. +15 (2 cp16)
    const int srow = tid >> 1;
    const int sch  = (tid & 1) * 16;
    const __half* Asrc = Ag + (size_t)(bm * GBM + srow) * K + sch;
    const __half* Bsrc = W  + (size_t)(bn * GBN + srow) * K + sch;

    const uint32_t aDst = smem_u32(As) + (srow * BKPH + sch) * 2;
    const uint32_t bDst = smem_u32(Bs) + (srow * BKPH + sch) * 2;

    float acc[2][8][4];
    #pragma unroll
    for (int mt = 0; mt < 2; mt++)
        #pragma unroll
        for (int nt = 0; nt < 8; nt++)
            #pragma unroll
            for (int e = 0; e < 4; e++) acc[mt][nt][e] = 0.0f;

    const int NS = K / GBK;

    #pragma unroll
    for (int st = 0; st < 3; st++) {
        const int k0 = st * GBK;
        cp16(aDst + st * GBM * BKPH * 2,      Asrc + k0);
        cp16(aDst + st * GBM * BKPH * 2 + 16, Asrc + k0 + 8);
        cp16(bDst + st * GBN * BKPH * 2,      Bsrc + k0);
        cp16(bDst + st * GBN * BKPH * 2 + 16, Bsrc + k0 + 8);
        CP_COMMIT();
    }

    for (int s = 0; s < NS; s++) {
        const int buf = s & 3;
        CP_WAIT(2);
        __syncthreads();

        if (s + 3 < NS) {
            const int nbuf = (s + 3) & 3;
            const int k0 = (s + 3) * GBK;
            cp16(aDst + nbuf * GBM * BKPH * 2,      Asrc + k0);
            cp16(aDst + nbuf * GBM * BKPH * 2 + 16, Asrc + k0 + 8);
            cp16(bDst + nbuf * GBN * BKPH * 2,      Bsrc + k0);
            cp16(bDst + nbuf * GBN * BKPH * 2 + 16, Bsrc + k0 + 8);
        }
        CP_COMMIT();

        const __half* Asb = &As[buf * GBM * BKPH];
        const __half* Bsb = &Bs[buf * GBN * BKPH];

        #pragma unroll
        for (int kk = 0; kk < 2; kk++) {        // two k16 chunks
            uint32_t af[2][4];
            #pragma unroll
            for (int mt = 0; mt < 2; mt++) {
                const __half* base = &Asb[(wm + mt * 16) * BKPH + kk * 16 + 2 * t];
                af[mt][0] = lds32(base + g * BKPH);
                af[mt][1] = lds32(base + (g + 8) * BKPH);
                af[mt][2] = lds32(base + g * BKPH + 8);
                af[mt][3] = lds32(base + (g + 8) * BKPH + 8);
            }
            #pragma unroll
            for (int nt = 0; nt < 8; nt++) {
                const __half* bb = &Bsb[(wn + nt * 8 + g) * BKPH + kk * 16 + 2 * t];
                const uint32_t b0 = lds32(bb);
                const uint32_t b1 = lds32(bb + 8);
                #pragma unroll
                for (int mt = 0; mt < 2; mt++)
                    mma_f16(acc[mt][nt], af[mt][0], af[mt][1], af[mt][2], af[mt][3],
                            b0, b1);
            }
        }
    }

    // ---- epilogue ----
    const float QSC = 0.125f * 1.4426950408889634f;
    #pragma unroll
    for (int mt = 0; mt < 2; mt++) {
        #pragma unroll
        for (int half_ = 0; half_ < 2; half_++) {      // rows g / g+8
            const int m = bm * GBM + wm + mt * 16 + g + half_ * 8;
            const int bb_ = m >> 11;
            const int srw = m & 2047;
            #pragma unroll
            for (int nt = 0; nt < 8; nt++) {
                const int n = bn * GBN + wn + nt * 8 + 2 * t;
                float2 bvv = *(const float2*)(bias + n);
                float2 v;
                v.x = acc[mt][nt][half_ * 2 + 0] + bvv.x;
                v.y = acc[mt][nt][half_ * 2 + 1] + bvv.y;
                if (MODE == 0) {
                    const int part = n >> 10;
                    const int hd = n & 1023;
                    const int hh = hd >> 6;
                    const int d = hd & 63;
                    if (part == 0) {            // Q: scale, fp16, [b,h,s,d]
                        const size_t off =
                            (((size_t)(bb_ * NHEADS + hh)) * SEQ + srw) * DHEAD + d;
                        *(__half2*)(g_qh + off) =
                            __floats2half2_rn(v.x * QSC, v.y * QSC);
                    } else if (part == 1) {     // K: fp16, [b,h,s,d]
                        const size_t off =
                            (((size_t)(bb_ * NHEADS + hh)) * SEQ + srw) * DHEAD + d;
                        *(__half2*)(g_kh + off) = __floats2half2_rn(v.x, v.y);
                    } else {                    // V: fp16 TRANSPOSED [b,h,d,s]
                        const size_t off =
                            (((size_t)(bb_ * NHEADS + hh)) * DHEAD + d) * SEQ + srw;
                        g_vt[off]       = __float2half_rn(v.x);
                        g_vt[off + SEQ] = __float2half_rn(v.y);
                    }
                } else {
                    *(float2*)(C + (size_t)m * N + n) = v;
                }
            }
        }
    }
}

// ===========================================================================
// Flash attention, FP16 mma.sync m16n8k16. 128-row q-tile, 256 thr = 8 warps
// x 16 q-rows. Base-2 softmax. All tiles stride 72 halves (conflict-free).
// Qs[128][72] (d-major), Ks[64 keys][72 d], Vts[64 d][72 keys], Ps[128][72].
// ===========================================================================
#define FSTRH 72
#define QTILE 128
#define FLASH_SMEM ((QTILE * FSTRH + 64 * FSTRH + 64 * FSTRH + QTILE * FSTRH) * 2)

__global__ __launch_bounds__(256) void flash_mma(const int* __restrict__ maskFlag)
{
    extern __shared__ __half smf[];
    __half* Ks  = smf;                     // [64 keys][FSTRH]
    __half* Vts = Ks + 64 * FSTRH;         // [64 d][FSTRH keys]
    __half* Qs  = Vts + 64 * FSTRH;        // [128 q][FSTRH]  (persistent)
    __half* Ps  = Qs + QTILE * FSTRH;      // [128 q][FSTRH keys]

    const int tid  = threadIdx.x;
    const int lane = tid & 31;
    const int w    = tid >> 5;
    const int g    = lane >> 2;
    const int t    = lane & 3;
    const int qt   = (int)gridDim.x - 1 - (int)blockIdx.x;  // heavy tiles first
    const int h    = blockIdx.y;
    const int b    = blockIdx.z;
    const int causal = maskFlag[0];

    const size_t bh = (size_t)(b * NHEADS + h) * SEQ * DHEAD;
    const __half* Qg  = g_qh + bh + (size_t)qt * QTILE * DHEAD;
    const __half* Kg  = g_kh + bh;
    const __half* Vtg = g_vt + bh;          // [d][s] within (b,h)

    const uint32_t ksU = smem_u32(Ks);
    const uint32_t vsU = smem_u32(Vts);
    const uint32_t qsU = smem_u32(Qs);

    // ---- stage Q (scaled fp16): 128 rows x 128B = 4 cp16 / thread ----
    #pragma unroll
    for (int j = 0; j < 4; j++) {
        const int i = tid + j * 256;
        const int r  = i >> 3;
        const int c8 = (i & 7) * 8;
        cp16(qsU + (r * FSTRH + c8) * 2, Qg + r * DHEAD + c8);
    }
    CP_COMMIT();

    float of[8][4];
    float mA = -CUDART_INF_F, mB = -CUDART_INF_F;
    float lA = 0.0f, lB = 0.0f;
    #pragma unroll
    for (int nt = 0; nt < 8; nt++)
        #pragma unroll
        for (int e = 0; e < 4; e++) of[nt][e] = 0.0f;

    const int ktEnd = causal ? (2 * qt + 1) : (SEQ / 64 - 1);

    for (int kt = 0; kt <= ktEnd; kt++) {
        __syncthreads();   // prev iter done reading Ks/Vts
        const __half* Kt = Kg + (size_t)kt * 64 * DHEAD;
        const __half* Vk = Vtg + (size_t)kt * 64;   // column offset in [d][s]
        #pragma unroll
        for (int j = 0; j < 2; j++) {
            const int i = tid + j * 256;
            const int r  = i >> 3;          // key row (K) / d row (V)
            const int c8 = (i & 7) * 8;
            cp16(ksU + (r * FSTRH + c8) * 2, Kt + r * DHEAD + c8);
            cp16(vsU + (r * FSTRH + c8) * 2, Vk + (size_t)r * SEQ + c8);
        }
        CP_COMMIT();
        CP_WAIT(0);
        __syncthreads();

        // ---- S = Q K^T (m16 x n64, k=64: 4 k16 chunks) ----
        float sf[8][4];
        #pragma unroll
        for (int nt = 0; nt < 8; nt++)
            #pragma unroll
            for (int e = 0; e < 4; e++) sf[nt][e] = 0.0f;

        #pragma unroll
        for (int kk = 0; kk < 4; kk++) {
            const __half* qb = &Qs[(w * 16) * FSTRH + kk * 16 + 2 * t];
            const uint32_t a0 = lds32(qb + g * FSTRH);
            const uint32_t a1 = lds32(qb + (g + 8) * FSTRH);
            const uint32_t a2 = lds32(qb + g * FSTRH + 8);
            const uint32_t a3 = lds32(qb + (g + 8) * FSTRH + 8);
            #pragma unroll
            for (int nt = 0; nt < 8; nt++) {
                const __half* kb = &Ks[(nt * 8 + g) * FSTRH + kk * 16 + 2 * t];
                mma_f16(sf[nt], a0, a1, a2, a3, lds32(kb), lds32(kb + 8));
            }
        }

        // ---- causal mask ----
        if (causal && (kt >= 2 * qt)) {
            const int rowb = qt * QTILE + w * 16;
            const int colb = kt * 64;
            #pragma unroll
            for (int nt = 0; nt < 8; nt++) {
                #pragma unroll
                for (int e = 0; e < 4; e++) {
                    const int col = colb + nt * 8 + 2 * t + (e & 1);
                    const int row = rowb + g + ((e >> 1) << 3);
                    if (col > row) sf[nt][e] = -CUDART_INF_F;
                }
            }
        }

        // ---- online softmax in base 2 (rows: A = g, B = g+8) ----
        float mxA = -CUDART_INF_F, mxB = -CUDART_INF_F;
        #pragma unroll
        for (int nt = 0; nt < 8; nt++) {
            mxA = fmaxf(mxA, fmaxf(sf[nt][0], sf[nt][1]));
            mxB = fmaxf(mxB, fmaxf(sf[nt][2], sf[nt][3]));
        }
        mxA = fmaxf(mxA, __shfl_xor_sync(0xffffffffu, mxA, 1));
        mxA = fmaxf(mxA, __shfl_xor_sync(0xffffffffu, mxA, 2));
        mxB = fmaxf(mxB, __shfl_xor_sync(0xffffffffu, mxB, 1));
        mxB = fmaxf(mxB, __shfl_xor_sync(0xffffffffu, mxB, 2));

        const float mnA = fmaxf(mA, mxA);
        const float mnB = fmaxf(mB, mxB);
        const float aA = exp2f(mA - mnA);
        const float aB = exp2f(mB - mnB);
        float sA = 0.0f, sB = 0.0f;
        #pragma unroll
        for (int nt = 0; nt < 8; nt++) {
            sf[nt][0] = exp2f(sf[nt][0] - mnA);
            sf[nt][1] = exp2f(sf[nt][1] - mnA);
            sf[nt][2] = exp2f(sf[nt][2] - mnB);
            sf[nt][3] = exp2f(sf[nt][3] - mnB);
            sA += sf[nt][0] + sf[nt][1];
            sB += sf[nt][2] + sf[nt][3];
        }
        sA += __shfl_xor_sync(0xffffffffu, sA, 1);
        sA += __shfl_xor_sync(0xffffffffu, sA, 2);
        sB += __shfl_xor_sync(0xffffffffu, sB, 1);
        sB += __shfl_xor_sync(0xffffffffu, sB, 2);
        lA = lA * aA + sA;
        lB = lB * aB + sB;
        mA = mnA;
        mB = mnB;
        #pragma unroll
        for (int nt = 0; nt < 8; nt++) {
            of[nt][0] *= aA; of[nt][1] *= aA;
            of[nt][2] *= aB; of[nt][3] *= aB;
        }

        // ---- write P as fp16 pairs (warp-private rows) ----
        #pragma unroll
        for (int nt = 0; nt < 8; nt++) {
            const int c = nt * 8 + 2 * t;
            *(__half2*)&Ps[(w * 16 + g) * FSTRH + c] =
                __floats2half2_rn(sf[nt][0], sf[nt][1]);
            *(__half2*)&Ps[(w * 16 + g + 8) * FSTRH + c] =
                __floats2half2_rn(sf[nt][2], sf[nt][3]);
        }
        __syncwarp();

        // ---- O += P V (m16 x n64, k=64 keys: 4 k16 chunks) ----
        #pragma unroll
        for (int kk = 0; kk < 4; kk++) {
            const __half* pb = &Ps[(w * 16) * FSTRH + kk * 16 + 2 * t];
            const uint32_t a0 = lds32(pb + g * FSTRH);
            const uint32_t a1 = lds32(pb + (g + 8) * FSTRH);
            const uint32_t a2 = lds32(pb + g * FSTRH + 8);
            const uint32_t a3 = lds32(pb + (g + 8) * FSTRH + 8);
            #pragma unroll
            for (int nt = 0; nt < 8; nt++) {
                const __half* vb = &Vts[(nt * 8 + g) * FSTRH + kk * 16 + 2 * t];
                mma_f16(of[nt], a0, a1, a2, a3, lds32(vb), lds32(vb + 8));
            }
        }
    }

    // ---- epilogue: normalize, fp16, store (A-operand of out-proj) ----
    const float iA = 1.0f / lA;
    const float iB = 1.0f / lB;
    const int qrow = qt * QTILE + w * 16;
    #pragma unroll
    for (int nt = 0; nt < 8; nt++) {
        const int d = h * 64 + nt * 8 + 2 * t;
        *(__half2*)(g_attnh + ((size_t)b * SEQ + qrow + g) * DMODEL + d) =
            __floats2half2_rn(of[nt][0] * iA, of[nt][1] * iA);
        *(__half2*)(g_attnh + ((size_t)b * SEQ + qrow + g + 8) * DMODEL + d) =
            __floats2half2_rn(of[nt][2] * iB, of[nt][3] * iB);
    }
}

// ---------------------------------------------------------------------------
extern "C" void kernel_launch(void* const* d_in, const int* in_sizes, int n_in,
                              void* d_out, int out_size)
{
    const float* x   = (const float*)d_in[0];
    const float* w1  = (const float*)d_in[1];
    const float* b1  = (const float*)d_in[2];
    const float* w2  = (const float*)d_in[3];
    const float* b2  = (const float*)d_in[4];
    const int*   msk = (const int*)  d_in[5];
    float* out = (float*)d_out;

    const int M = BATCH * SEQ;   // 8192

    cudaFuncSetAttribute(gemm_mma<0>,
                         cudaFuncAttributeMaxDynamicSharedMemorySize, GEMM_SMEM);
    cudaFuncSetAttribute(gemm_mma<1>,
                         cudaFuncAttributeMaxDynamicSharedMemorySize, GEMM_SMEM);
    cudaFuncSetAttribute(flash_mma,
                         cudaFuncAttributeMaxDynamicSharedMemorySize, FLASH_SMEM);

    // 0) convert inputs to fp16
    __half* d_xh;  cudaGetSymbolAddress((void**)&d_xh,  g_xh);
    __half* d_w1h; cudaGetSymbolAddress((void**)&d_w1h, g_w1h);
    __half* d_w2h; cudaGetSymbolAddress((void**)&d_w2h, g_w2h);
    {
        const int nx = M * DMODEL / 8;
        to_f16_k<<<(nx + 255) / 256, 256>>>(x, d_xh, nx);
        const int n1 = 3 * DMODEL * DMODEL / 8;
        to_f16_k<<<(n1 + 255) / 256, 256>>>(w1, d_w1h, n1);
        const int n2 = DMODEL * DMODEL / 8;
        to_f16_k<<<(n2 + 255) / 256, 256>>>(w2, d_w2h, n2);
    }

    // 1) QKV projection -> g_qh (scaled) / g_kh / g_vt (transposed)
    gemm_mma<0><<<dim3(3 * DMODEL / GBN, M / GBM), 256, GEMM_SMEM>>>(
        d_w1h, b1, nullptr, M, 3 * DMODEL, DMODEL);

    // 2) Flash attention -> g_attnh
    flash_mma<<<dim3(SEQ / QTILE, NHEADS, BATCH), 256, FLASH_SMEM>>>(msk);

    // 3) Output projection -> d_out (fp32 + bias)
    gemm_mma<1><<<dim3(DMODEL / GBN, M / GBM), 256, GEMM_SMEM>>>(
        d_w2h, b2, out, M, DMODEL, DMODEL);
}